// round 16
// baseline (speedup 1.0000x reference)
#include <cuda_runtime.h>
#include <math.h>

#define N_ROWS   131072
#define IN_D     12
#define HID      256
#define NL       10
#define OUT_D    3
#define TM       32                 // rows per CTA
#define KC       16                 // k-chunk staged per cp.async group
#define NCHUNK   (HID / KC)         // 16 chunks per layer
#define NTHREADS 256
#define TOTAL_CHUNKS ((NL - 1) * NCHUNK)   // 144 flat chunks
#define HROW     (2 * TM)           // duplicated H row: 64 floats per k

typedef unsigned long long u64;

// packed fp32x2 FMA: d = a*b + d
__device__ __forceinline__ void fma2(u64& d, u64 a, u64 b) {
    asm("fma.rn.f32x2 %0, %1, %2, %0;" : "+l"(d) : "l"(a), "l"(b));
}
__device__ __forceinline__ float2 unpk2(u64 p) {
    float lo, hi;
    asm("mov.b64 {%0, %1}, %2;" : "=f"(lo), "=f"(hi) : "l"(p));
    return make_float2(lo, hi);
}

// act: 0=sin 1=cos 2=gauss 3=tanh
__device__ __forceinline__ float actf(float v, int mode) {
    switch (mode) {
        case 0:  return sinf(v);
        case 1:  return cosf(v);
        case 2:  return expf(-v * v);
        default: return tanhf(v);
    }
}

// Stage flat chunk tc (16x256 floats) of Ws into wbuf via cp.async (one group).
__device__ __forceinline__ void cp_chunk(const float4* __restrict__ Wv,
                                         int tc, float* wbuf, int tid) {
    const float4* src = Wv + (size_t)tc * (KC * HID / 4) + tid;
    unsigned dst = (unsigned)__cvta_generic_to_shared(wbuf) + tid * 16u;
    #pragma unroll
    for (int r = 0; r < 4; r++) {
        asm volatile("cp.async.cg.shared.global [%0], [%1], 16;\n"
                     :: "r"(dst + r * (NTHREADS * 16u)), "l"(src + r * NTHREADS));
    }
    asm volatile("cp.async.commit_group;\n" ::: "memory");
}

// 4m x 8n k-step. H is stored DUPLICATED: hp[2m]={h_m,h_m}. Both the a-pairs
// and the W n-pairs load directly as u64 — zero mov/dup instructions.
// accp[i][j] = row m0+i, cols (n0+2j, n0+2j+1).
__device__ __forceinline__ void kstep(u64 accp[4][4], const float* hp, const float* wp,
                                      int m0, int n0) {
    const ulonglong2 A0 = *(const ulonglong2*)(hp + 2 * m0);      // {m0},{m0+1}
    const ulonglong2 A1 = *(const ulonglong2*)(hp + 2 * m0 + 4);  // {m0+2},{m0+3}
    const ulonglong2 W0 = *(const ulonglong2*)(wp + n0);          // n-pairs 0,1
    const ulonglong2 W1 = *(const ulonglong2*)(wp + n0 + 4);      // n-pairs 2,3
    u64 ad[4] = {A0.x, A0.y, A1.x, A1.y};
    u64 wd[4] = {W0.x, W0.y, W1.x, W1.y};
    #pragma unroll
    for (int i = 0; i < 4; i++)
        #pragma unroll
        for (int j = 0; j < 4; j++)
            fma2(accp[i][j], ad[i], wd[j]);
}

// store 4 activated values (rows m0..m0+3, col n) duplicated
__device__ __forceinline__ void store_dup4(float* hrow, int m0,
                                           float v0, float v1, float v2, float v3) {
    float4 p0 = {v0, v0, v1, v1};
    float4 p1 = {v2, v2, v3, v3};
    *(float4*)(hrow + 2 * m0)     = p0;
    *(float4*)(hrow + 2 * m0 + 4) = p1;
}

__global__ void __launch_bounds__(NTHREADS, 2)
cppn_kernel(const float* __restrict__ x,
            const float* __restrict__ W0,
            const float* __restrict__ b0,
            const float* __restrict__ Ws,
            const float* __restrict__ bs,
            const float* __restrict__ Wout,
            const float* __restrict__ bout,
            float* __restrict__ out)
{
    extern __shared__ float sm[];
    float* hc  = sm;                    // [HID][2*TM] duplicated activations, 64 KB
    float* wb0 = sm + HID * HROW;       // [KC][HID] weight stage buffer 0 (16 KB)
    float* wb1 = wb0 + KC * HID;        // [KC][HID] weight stage buffer 1 (16 KB)

    const int tid  = threadIdx.x;
    const int row0 = blockIdx.x * TM;
    const int m0   = (tid & 7) * 4;     // 4 m-rows per thread
    const int n0   = (tid >> 3) * 8;    // 8 n-cols per thread
    const float4* Wv = (const float4*)Ws;

    u64 accp[4][4];
    const u64 Z = 0ull;

    // ---- prologue: start staging hidden chunk 0 into wb0 ----
    cp_chunk(Wv, 0, wb0, tid);

    // ======================= layer 0: x(12) -> 256, sin =======================
    {
        float* w0s = wb1;                       // 12 KB
        float* xs  = wb1 + IN_D * HID;          // duplicated x: 12*64 floats, 3 KB
        const float4* W0v = (const float4*)W0;
        float4* wa = (float4*)w0s;
        #pragma unroll
        for (int idx = tid; idx < IN_D * HID / 4; idx += NTHREADS) wa[idx] = W0v[idx];
        for (int idx = tid; idx < TM * IN_D; idx += NTHREADS) {
            int m = idx / IN_D, k = idx % IN_D;
            float v = x[(size_t)(row0 + m) * IN_D + k];
            xs[k * HROW + 2 * m]     = v;
            xs[k * HROW + 2 * m + 1] = v;
        }
        __syncthreads();

        #pragma unroll
        for (int i = 0; i < 4; i++)
            #pragma unroll
            for (int j = 0; j < 4; j++) accp[i][j] = Z;

        #pragma unroll
        for (int k = 0; k < IN_D; k++)
            kstep(accp, xs + k * HROW, w0s + k * HID, m0, n0);

        // bias + sin -> hc (duplicated)
        #pragma unroll
        for (int j = 0; j < 4; j++) {
            const float2 bb = *(const float2*)(b0 + n0 + 2 * j);
            float2 p0 = unpk2(accp[0][j]), p1 = unpk2(accp[1][j]);
            float2 p2 = unpk2(accp[2][j]), p3 = unpk2(accp[3][j]);
            store_dup4(hc + (n0 + 2 * j) * HROW, m0,
                       actf(p0.x + bb.x, 0), actf(p1.x + bb.x, 0),
                       actf(p2.x + bb.x, 0), actf(p3.x + bb.x, 0));
            store_dup4(hc + (n0 + 2 * j + 1) * HROW, m0,
                       actf(p0.y + bb.y, 0), actf(p1.y + bb.y, 0),
                       actf(p2.y + bb.y, 0), actf(p3.y + bb.y, 0));
        }
    }

    // ======================= hidden layers 1..9: 256 -> 256 ===================
    int t = 0;   // flat chunk counter
    for (int layer = 1; layer < NL; layer++) {
        const int mode = layer & 3;

        #pragma unroll
        for (int i = 0; i < 4; i++)
            #pragma unroll
            for (int j = 0; j < 4; j++) accp[i][j] = Z;

        #pragma unroll 1
        for (int c = 0; c < NCHUNK; c++, t++) {
            asm volatile("cp.async.wait_group 0;\n" ::: "memory");
            __syncthreads();
            if (t + 1 < TOTAL_CHUNKS)
                cp_chunk(Wv, t + 1, (t & 1) ? wb0 : wb1, tid);

            const float* Wbuf = (t & 1) ? wb1 : wb0;
            const float* hrow = hc + c * KC * HROW;

            #pragma unroll 4
            for (int kk = 0; kk < KC; kk++)
                kstep(accp, hrow + kk * HROW, Wbuf + kk * HID, m0, n0);
        }

        // epilogue: all reads of hc for this layer done -> overwrite in place
        __syncthreads();
        const float* bias = bs + (layer - 1) * HID;
        #pragma unroll
        for (int j = 0; j < 4; j++) {
            const float2 bb = *(const float2*)(bias + n0 + 2 * j);
            float2 p0 = unpk2(accp[0][j]), p1 = unpk2(accp[1][j]);
            float2 p2 = unpk2(accp[2][j]), p3 = unpk2(accp[3][j]);
            store_dup4(hc + (n0 + 2 * j) * HROW, m0,
                       actf(p0.x + bb.x, mode), actf(p1.x + bb.x, mode),
                       actf(p2.x + bb.x, mode), actf(p3.x + bb.x, mode));
            store_dup4(hc + (n0 + 2 * j + 1) * HROW, m0,
                       actf(p0.y + bb.y, mode), actf(p1.y + bb.y, mode),
                       actf(p2.y + bb.y, mode), actf(p3.y + bb.y, mode));
        }
        // published by the barrier at the top of next layer's first chunk
    }

    // ======================= output layer: 256 -> 3, sigmoid ==================
    __syncthreads();
    if (tid < TM * OUT_D) {                 // 96 threads: one (row, col) each
        const int m = tid / OUT_D;
        const int j = tid % OUT_D;
        float s = bout[j];
        #pragma unroll 8
        for (int k = 0; k < HID; k++)
            s = fmaf(hc[k * HROW + 2 * m], Wout[k * OUT_D + j], s);
        out[(size_t)(row0 + m) * OUT_D + j] = 1.0f / (1.0f + expf(-s));
    }
}

extern "C" void kernel_launch(void* const* d_in, const int* in_sizes, int n_in,
                              void* d_out, int out_size)
{
    const float* x    = (const float*)d_in[0];
    const float* W0   = (const float*)d_in[1];
    const float* b0   = (const float*)d_in[2];
    const float* Ws   = (const float*)d_in[3];
    const float* bs   = (const float*)d_in[4];
    const float* Wout = (const float*)d_in[5];
    const float* bout = (const float*)d_in[6];
    float* out = (float*)d_out;

    const int smem_bytes = (HID * HROW + 2 * KC * HID) * (int)sizeof(float); // 96 KB
    cudaFuncSetAttribute(cppn_kernel, cudaFuncAttributeMaxDynamicSharedMemorySize, smem_bytes);

    dim3 grid(N_ROWS / TM);   // 4096 CTAs, 2 resident per SM
    dim3 block(NTHREADS);
    cppn_kernel<<<grid, block, smem_bytes>>>(x, W0, b0, Ws, bs, Wout, bout, out);
}